// round 14
// baseline (speedup 1.0000x reference)
#include <cuda_runtime.h>
#include <math.h>

#define LEVELS 16
#define TABLE_SIZE 524288
#define HMASK (TABLE_SIZE - 1)
#define NPTS 1048576
#define PRIME 2654435761u
#define THREADS 256
#define GRID_B 512                        // 512 x 512 Morton buckets
#define NBUCKETS (GRID_B * GRID_B)        // 262144
#define CTAS 512                          // fused sort kernel grid
#define TPB 256
#define PTS_PER (NPTS / (CTAS * TPB))     // 8 points per thread
#define ENT_PER_CTA (NBUCKETS / CTAS)     // 512 buckets per CTA
#define SSTR2 9                           // staging stride in float2 (8 + pad)

struct ResArr { float r[LEVELS]; };

typedef unsigned long long u64;

// Scratch (__device__ globals: the sanctioned no-allocation path)
__device__ int    d_hist[NBUCKETS];       // zero-init at load; gather tail re-zeros
__device__ int    d_bar1;                 // global-barrier counters / flag —
__device__ int    d_bar2;                 //   reset by gather tail
__device__ int    d_flag;
__device__ int    d_offs[NBUCKETS];
__device__ int    d_bsum[CTAS];
__device__ int    d_bbase[CTAS];
__device__ float4 d_pts[NPTS];            // (x, y, bitcast(orig index), pad)

// ---- packed f32x2 helpers (sm_100+) ----
__device__ __forceinline__ u64 bcast2(float a) {
    u64 r; asm("mov.b64 %0, {%1, %1};" : "=l"(r) : "f"(a)); return r;
}
__device__ __forceinline__ u64 sub2(u64 a, u64 b) {
    u64 r; asm("sub.rn.f32x2 %0, %1, %2;" : "=l"(r) : "l"(a), "l"(b)); return r;
}
__device__ __forceinline__ u64 fma2(u64 a, u64 b, u64 c) {
    u64 r; asm("fma.rn.f32x2 %0, %1, %2, %3;" : "=l"(r) : "l"(a), "l"(b), "l"(c)); return r;
}
__device__ __forceinline__ void unpack2(u64 v, float& lo, float& hi) {
    asm("mov.b64 {%0, %1}, %2;" : "=f"(lo), "=f"(hi) : "l"(v));
}

__device__ __forceinline__ unsigned expand16(unsigned v) {
    v = (v | (v << 8)) & 0x00FF00FFu;
    v = (v | (v << 4)) & 0x0F0F0F0Fu;
    v = (v | (v << 2)) & 0x33333333u;
    v = (v | (v << 1)) & 0x55555555u;
    return v;
}
__device__ __forceinline__ unsigned bucket_of(float px, float py) {
    unsigned bx = (unsigned)(int)(px * (float)GRID_B);
    unsigned by = (unsigned)(int)(py * (float)GRID_B);
    bx = bx > (GRID_B - 1u) ? (GRID_B - 1u) : bx;
    by = by > (GRID_B - 1u) ? (GRID_B - 1u) : by;
    return expand16(bx) | (expand16(by) << 1);
}

// 256-thread scan helper: thread owns entries (2*tid, 2*tid+1) of a
// 512-entry chunk. Returns exclusive prefix of entry 2*tid; total via ptr.
__device__ __forceinline__ int scan512(int e0, int e1, int tid, int* s_w,
                                       int* total)
{
    int lane = tid & 31, wp = tid >> 5;
    int pair = e0 + e1;
    int s = pair;
#pragma unroll
    for (int o = 1; o < 32; o <<= 1) {
        int u = __shfl_up_sync(0xFFFFFFFFu, s, o);
        if (lane >= o) s += u;
    }
    if (lane == 31) s_w[wp] = s;
    __syncthreads();
    if (wp == 0 && lane < 8) {
        int ws = s_w[lane];
        int wi = ws;
#pragma unroll
        for (int o = 1; o < 8; o <<= 1) {
            int u = __shfl_up_sync(0x000000FFu, wi, o);
            if (lane >= o) wi += u;
        }
        s_w[lane] = wi - ws;               // exclusive warp base
        if (lane == 7) s_w[8] = wi;        // chunk total
    }
    __syncthreads();
    int excl = s - pair + s_w[wp];
    *total = s_w[8];
    return excl;
}

// Fused counting sort: histogram -> scan -> scatter, one resident kernel.
// Residency: __launch_bounds__(TPB, 4) => >=4 CTAs/SM * 148 = 592 >= CTAS,
// so the spin barriers cannot deadlock.
__global__ __launch_bounds__(TPB, 4)
void sort_kernel(const float2* __restrict__ x) {
    __shared__ int s_w[9];
    __shared__ int s_last;
    int tid = threadIdx.x;
    int cta = blockIdx.x;
    const int Q = NPTS / PTS_PER;          // 131072
    int t = cta * TPB + tid;

    // ---- Phase 1: histogram (points cached in registers) ----
    float2   p[PTS_PER];
    unsigned b[PTS_PER];
#pragma unroll
    for (int k = 0; k < PTS_PER; ++k) {
        p[k] = x[t + k * Q];
        b[k] = bucket_of(p[k].x, p[k].y);
    }
#pragma unroll
    for (int k = 0; k < PTS_PER; ++k)
        atomicAdd(&d_hist[b[k]], 1);

    // ---- Global barrier 1: all histogram updates visible ----
    __threadfence();
    __syncthreads();
    if (tid == 0) {
        atomicAdd(&d_bar1, 1);
        while (atomicAdd(&d_bar1, 0) < CTAS) __nanosleep(64);
    }
    __syncthreads();

    // ---- Phase 2: scan this CTA's 512-bucket chunk ----
    int base = cta * ENT_PER_CTA;
    int i0 = base + 2 * tid;
    int e0 = d_hist[i0], e1 = d_hist[i0 + 1];
    int total;
    int excl = scan512(e0, e1, tid, s_w, &total);
    d_offs[i0]     = excl;
    d_offs[i0 + 1] = excl + e0;
    if (tid == 0) d_bsum[cta] = total;

    // ---- Global barrier 2: last CTA scans the 512 chunk totals ----
    __threadfence();
    __syncthreads();
    if (tid == 0) s_last = (atomicAdd(&d_bar2, 1) == CTAS - 1);
    __syncthreads();
    if (s_last) {
        int f0 = d_bsum[2 * tid], f1 = d_bsum[2 * tid + 1];
        int tot2;
        int ex2 = scan512(f0, f1, tid, s_w, &tot2);
        d_bbase[2 * tid]     = ex2;
        d_bbase[2 * tid + 1] = ex2 + f0;
        __threadfence();
        __syncthreads();
        if (tid == 0) atomicExch(&d_flag, 1);
    }
    if (tid == 0) {
        while (atomicAdd(&d_flag, 0) == 0) __nanosleep(64);
    }
    __syncthreads();

    // ---- Phase 3: scatter from registers (batched atomics, MLP) ----
    int pos[PTS_PER];
#pragma unroll
    for (int k = 0; k < PTS_PER; ++k)
        pos[k] = d_bbase[b[k] >> 9] + atomicAdd(&d_offs[b[k]], 1);
#pragma unroll
    for (int k = 0; k < PTS_PER; ++k)
        d_pts[pos[k]] = make_float4(p[k].x, p[k].y,
                                    __int_as_float(t + k * Q), 0.0f);
}

__global__ __launch_bounds__(THREADS, 8)
void hashenc_kernel(const float2* __restrict__ tables,
                    float* __restrict__ out,
                    ResArr res)
{
    __shared__ float2 s2[THREADS * SSTR2];    // 18.4 KB
    __shared__ int    s_idx[THREADS];         // 1 KB
    int tid  = threadIdx.x;
    int lane = tid & 31;
    int w    = tid >> 5;
    int j    = blockIdx.x * THREADS + tid;

    float4 pk = d_pts[j];
    float px = pk.x, py = pk.y;
    s_idx[tid] = __float_as_int(pk.z);

    const u64* tu = reinterpret_cast<const u64*>(tables);

#pragma unroll
    for (int ph = 0; ph < 2; ++ph) {
        if (ph) __syncthreads();              // writes done before restage
        float a0e = 0.0f, a1e = 0.0f;
#pragma unroll
        for (int li = 0; li < 8; ++li) {
            const int l = ph * 8 + li;
            const u64* t = tu + (size_t)l * TABLE_SIZE;
            float r  = res.r[l];
            float sx = px * r;
            float sy = py * r;
            float gxf = floorf(sx);
            float gyf = floorf(sy);
            float fx = sx - gxf;
            float fy = sy - gyf;

            unsigned gx = (unsigned)(int)gxf;
            unsigned gy = (unsigned)(int)gyf;
            unsigned hy0 = gy * PRIME;
            unsigned hy1 = hy0 + PRIME;

            u64 F00 = __ldg(t + (( gx        ^ hy0) & HMASK));
            u64 F10 = __ldg(t + (((gx + 1u)  ^ hy0) & HMASK));
            u64 F01 = __ldg(t + (( gx        ^ hy1) & HMASK));
            u64 F11 = __ldg(t + (((gx + 1u)  ^ hy1) & HMASK));

            // A = fy*(fx*F00 + (1-fx)*F10) + (1-fy)*(fx*F01 + (1-fx)*F11)
            u64 FX = bcast2(fx);
            u64 FY = bcast2(fy);
            u64 I0 = fma2(FX, sub2(F00, F10), F10);
            u64 I1 = fma2(FX, sub2(F01, F11), F11);
            u64 A  = fma2(FY, sub2(I0, I1), I1);

            float a0, a1;
            unpack2(A, a0, a1);

            if (li & 1) {                     // STS.64 per level-pair
                s2[tid * SSTR2 + (li >> 1)]     = make_float2(a0e, a0);
                s2[tid * SSTR2 + 4 + (li >> 1)] = make_float2(a1e, a1);
            } else { a0e = a0; a1e = a1; }
        }
        __syncthreads();

        // Write loop: lane handles one float2 (two adjacent out columns);
        // warp covers 4 rows x 8 slots per iteration -> 8 iterations/phase.
        int c    = lane & 7;
        int rsub = lane >> 3;
        int col  = (c < 4) ? (ph * 8 + 2 * c) : (8 + ph * 8 + 2 * c);
        for (int k = w; k < THREADS / 4; k += THREADS / 32) {
            int rrow = 4 * k + rsub;
            int nn = s_idx[rrow];             // broadcast LDS
            float2 v = s2[rrow * SSTR2 + c];
            *reinterpret_cast<float2*>(&out[(size_t)nn * 32 + col]) = v;
        }
    }

    // Tail: zero hist + barrier state for the next call — effectively free
    // here (overlaps kernel drain). Globals are zero-initialized at module
    // load, so the first call is also correct.
    int g = blockIdx.x * THREADS + tid;
    if (g < NBUCKETS) d_hist[g] = 0;
    if (g == 0) { d_bar1 = 0; d_bar2 = 0; d_flag = 0; }
}

extern "C" void kernel_launch(void* const* d_in, const int* in_sizes, int n_in,
                              void* d_out, int out_size)
{
    // Exact float64 replication of the reference _RESOLUTIONS computation.
    ResArr res;
    double b = exp((log(512.0) - log(16.0)) / 15.0);
    for (int l = 0; l < LEVELS; ++l) {
        double pw;
        if (l == 0)      pw = 1.0;
        else if (l == 1) pw = b;
        else             pw = pow(b, (double)l);
        res.r[l] = (float)floor(16.0 * pw);
    }

    const float2* x      = (const float2*)d_in[0];
    const float2* tables = (const float2*)d_in[1];
    float*        out    = (float*)d_out;

    sort_kernel<<<CTAS, TPB>>>(x);
    hashenc_kernel<<<NPTS / THREADS, THREADS>>>(tables, out, res);
}

// round 15
// speedup vs baseline: 1.0485x; 1.0485x over previous
#include <cuda_runtime.h>
#include <math.h>

#define LEVELS 16
#define TABLE_SIZE 524288
#define HMASK (TABLE_SIZE - 1)
#define NPTS 1048576
#define PRIME 2654435761u
#define THREADS 256
#define GRID_B 512                        // 512 x 512 Morton buckets
#define NBUCKETS (GRID_B * GRID_B)        // 262144
#define SCAN_BLK 1024
#define NSCANBLK (NBUCKETS / SCAN_BLK)    // 256
#define SC_PER 8                          // points per scatter thread (MLP)
#define HI_PER 8                          // points per hist thread (MLP)
#define SSTR2 9                           // staging stride in float2 (8 + pad)

struct ResArr { float r[LEVELS]; };

typedef unsigned long long u64;

// Scratch (__device__ globals: the sanctioned no-allocation path)
__device__ int    d_hist[NBUCKETS];       // zero-init at load; gather tail re-zeros
__device__ int    d_done;                 // reset by gather tail
__device__ int    d_offs[NBUCKETS];
__device__ int    d_bsum[NSCANBLK];
__device__ int    d_bbase[NSCANBLK];
__device__ float4 d_pts[NPTS];            // (x, y, bitcast(orig index), pad)

// ---- packed f32x2 helpers (sm_100+) ----
__device__ __forceinline__ u64 bcast2(float a) {
    u64 r; asm("mov.b64 %0, {%1, %1};" : "=l"(r) : "f"(a)); return r;
}
__device__ __forceinline__ u64 sub2(u64 a, u64 b) {
    u64 r; asm("sub.rn.f32x2 %0, %1, %2;" : "=l"(r) : "l"(a), "l"(b)); return r;
}
__device__ __forceinline__ u64 fma2(u64 a, u64 b, u64 c) {
    u64 r; asm("fma.rn.f32x2 %0, %1, %2, %3;" : "=l"(r) : "l"(a), "l"(b), "l"(c)); return r;
}
__device__ __forceinline__ void unpack2(u64 v, float& lo, float& hi) {
    asm("mov.b64 {%0, %1}, %2;" : "=f"(lo), "=f"(hi) : "l"(v));
}

__device__ __forceinline__ unsigned expand16(unsigned v) {
    v = (v | (v << 8)) & 0x00FF00FFu;
    v = (v | (v << 4)) & 0x0F0F0F0Fu;
    v = (v | (v << 2)) & 0x33333333u;
    v = (v | (v << 1)) & 0x55555555u;
    return v;
}
__device__ __forceinline__ unsigned bucket_of(float px, float py) {
    unsigned bx = (unsigned)(int)(px * (float)GRID_B);
    unsigned by = (unsigned)(int)(py * (float)GRID_B);
    bx = bx > (GRID_B - 1u) ? (GRID_B - 1u) : bx;
    by = by > (GRID_B - 1u) ? (GRID_B - 1u) : by;
    return expand16(bx) | (expand16(by) << 1);
}

// 8 points per thread via four coalesced float4 loads; batched atomics.
__global__ __launch_bounds__(THREADS)
void hist_kernel(const float4* __restrict__ x4) {
    const int QH = NPTS / 8;
    int t = blockIdx.x * blockDim.x + threadIdx.x;
    float4 q[4];
#pragma unroll
    for (int k = 0; k < 4; ++k) q[k] = x4[t + k * QH];
#pragma unroll
    for (int k = 0; k < 4; ++k) {
        atomicAdd(&d_hist[bucket_of(q[k].x, q[k].y)], 1);
        atomicAdd(&d_hist[bucket_of(q[k].z, q[k].w)], 1);
    }
    cudaTriggerProgrammaticLaunchCompletion();
}

// Warp-shuffle exclusive scan per 1024-entry chunk;
// the LAST block also scans the 256 chunk sums.
__global__ __launch_bounds__(SCAN_BLK)
void scan_kernel() {
    __shared__ int s_wsum[32];
    __shared__ int s_chunk;
    __shared__ bool is_last;
    int t    = threadIdx.x;
    int lane = t & 31;
    int wp   = t >> 5;
    int i    = blockIdx.x * SCAN_BLK + t;

    cudaGridDependencySynchronize();       // wait for hist's writes

    int v = d_hist[i];

    // warp inclusive scan
    int s = v;
#pragma unroll
    for (int o = 1; o < 32; o <<= 1) {
        int u = __shfl_up_sync(0xFFFFFFFFu, s, o);
        if (lane >= o) s += u;
    }
    if (lane == 31) s_wsum[wp] = s;
    __syncthreads();
    if (wp == 0) {                         // scan the 32 warp totals
        int ws = s_wsum[lane];
        int wi = ws;
#pragma unroll
        for (int o = 1; o < 32; o <<= 1) {
            int u = __shfl_up_sync(0xFFFFFFFFu, wi, o);
            if (lane >= o) wi += u;
        }
        s_wsum[lane] = wi - ws;            // exclusive warp base
        if (lane == 31) s_chunk = wi;      // chunk total
    }
    __syncthreads();
    d_offs[i] = s + s_wsum[wp] - v;        // exclusive within chunk
    if (t == SCAN_BLK - 1) d_bsum[blockIdx.x] = s_chunk;

    __threadfence();
    if (t == 0) is_last = (atomicAdd(&d_done, 1) == NSCANBLK - 1);
    __syncthreads();
    if (is_last) {                         // block-uniform branch
        if (wp < NSCANBLK / 32) {          // 8 warps cover 256 sums
            int idx = wp * 32 + lane;
            int bv = d_bsum[idx];
            int bs = bv;
#pragma unroll
            for (int o = 1; o < 32; o <<= 1) {
                int u = __shfl_up_sync(0xFFFFFFFFu, bs, o);
                if (lane >= o) bs += u;
            }
            if (lane == 31) s_wsum[wp] = bs;   // per-warp totals of sums
        }
        __syncthreads();
        if (wp == 0 && lane < NSCANBLK / 32) {
            int ws = s_wsum[lane];
            int wi = ws;
#pragma unroll
            for (int o = 1; o < 8; o <<= 1) {
                int u = __shfl_up_sync(0x000000FFu, wi, o);
                if (lane >= o) wi += u;
            }
            s_wsum[lane] = wi - ws;
        }
        __syncthreads();
        if (wp < NSCANBLK / 32) {
            int idx = wp * 32 + lane;
            int bv = d_bsum[idx];
            int bs = bv;
#pragma unroll
            for (int o = 1; o < 32; o <<= 1) {
                int u = __shfl_up_sync(0xFFFFFFFFu, bs, o);
                if (lane >= o) bs += u;
            }
            d_bbase[idx] = bs - bv + s_wsum[wp];
        }
    }
}

// 8 points per thread. Pre-sync section (point loads + bucket computation)
// overlaps the scan via PDL; sync before touching d_offs/d_bbase.
__global__ __launch_bounds__(THREADS)
void scatter_kernel(const float2* __restrict__ x) {
    const int Q = NPTS / SC_PER;
    int t = blockIdx.x * blockDim.x + threadIdx.x;
    float2   p[SC_PER];
    unsigned b[SC_PER];
    int      pos[SC_PER];
#pragma unroll
    for (int k = 0; k < SC_PER; ++k) {
        p[k] = x[t + k * Q];
        b[k] = bucket_of(p[k].x, p[k].y);
    }

    cudaGridDependencySynchronize();       // wait for scan's d_offs/d_bbase

#pragma unroll
    for (int k = 0; k < SC_PER; ++k)
        pos[k] = d_bbase[b[k] >> 10] + atomicAdd(&d_offs[b[k]], 1);
#pragma unroll
    for (int k = 0; k < SC_PER; ++k)
        d_pts[pos[k]] = make_float4(p[k].x, p[k].y,
                                    __int_as_float(t + k * Q), 0.0f);
}

__global__ __launch_bounds__(THREADS, 8)
void hashenc_kernel(const float2* __restrict__ tables,
                    float* __restrict__ out,
                    ResArr res)
{
    __shared__ float2 s2[THREADS * SSTR2];    // 18.4 KB
    __shared__ int    s_idx[THREADS];         // 1 KB
    int tid  = threadIdx.x;
    int lane = tid & 31;
    int w    = tid >> 5;
    int j    = blockIdx.x * THREADS + tid;

    cudaGridDependencySynchronize();          // wait for scatter's d_pts

    float4 pk = d_pts[j];
    float px = pk.x, py = pk.y;
    s_idx[tid] = __float_as_int(pk.z);

    const u64* tu = reinterpret_cast<const u64*>(tables);

#pragma unroll
    for (int ph = 0; ph < 2; ++ph) {
        if (ph) __syncthreads();              // writes done before restage
        float a0e = 0.0f, a1e = 0.0f;
#pragma unroll
        for (int li = 0; li < 8; ++li) {
            const int l = ph * 8 + li;
            const u64* t = tu + (size_t)l * TABLE_SIZE;
            float r  = res.r[l];
            float sx = px * r;
            float sy = py * r;
            float gxf = floorf(sx);
            float gyf = floorf(sy);
            float fx = sx - gxf;
            float fy = sy - gyf;

            unsigned gx = (unsigned)(int)gxf;
            unsigned gy = (unsigned)(int)gyf;
            unsigned hy0 = gy * PRIME;
            unsigned hy1 = hy0 + PRIME;

            u64 F00 = __ldg(t + (( gx        ^ hy0) & HMASK));
            u64 F10 = __ldg(t + (((gx + 1u)  ^ hy0) & HMASK));
            u64 F01 = __ldg(t + (( gx        ^ hy1) & HMASK));
            u64 F11 = __ldg(t + (((gx + 1u)  ^ hy1) & HMASK));

            // A = fy*(fx*F00 + (1-fx)*F10) + (1-fy)*(fx*F01 + (1-fx)*F11)
            u64 FX = bcast2(fx);
            u64 FY = bcast2(fy);
            u64 I0 = fma2(FX, sub2(F00, F10), F10);
            u64 I1 = fma2(FX, sub2(F01, F11), F11);
            u64 A  = fma2(FY, sub2(I0, I1), I1);

            float a0, a1;
            unpack2(A, a0, a1);

            if (li & 1) {                     // STS.64 per level-pair
                s2[tid * SSTR2 + (li >> 1)]     = make_float2(a0e, a0);
                s2[tid * SSTR2 + 4 + (li >> 1)] = make_float2(a1e, a1);
            } else { a0e = a0; a1e = a1; }
        }
        __syncthreads();

        // Write loop: lane handles one float2 (two adjacent out columns);
        // warp covers 4 rows x 8 slots per iteration -> 8 iterations/phase.
        int c    = lane & 7;
        int rsub = lane >> 3;
        int col  = (c < 4) ? (ph * 8 + 2 * c) : (8 + ph * 8 + 2 * c);
        for (int k = w; k < THREADS / 4; k += THREADS / 32) {
            int rrow = 4 * k + rsub;
            int nn = s_idx[rrow];             // broadcast LDS
            float2 v = s2[rrow * SSTR2 + c];
            *reinterpret_cast<float2*>(&out[(size_t)nn * 32 + col]) = v;
        }
    }

    // Tail: zero hist + d_done for the next call — effectively free here
    // (overlaps kernel drain). Globals are zero-initialized at module load,
    // so the first call is also correct.
    int g = blockIdx.x * THREADS + tid;
    if (g < NBUCKETS) d_hist[g] = 0;
    if (g == 0) d_done = 0;
}

template <typename K, typename... Args>
static void launch_pdl(K kernel, dim3 grid, dim3 block, Args... args)
{
    cudaLaunchConfig_t cfg = {};
    cfg.gridDim  = grid;
    cfg.blockDim = block;
    cfg.stream   = 0;
    cudaLaunchAttribute a[1];
    a[0].id = cudaLaunchAttributeProgrammaticStreamSerialization;
    a[0].val.programmaticStreamSerializationAllowed = 1;
    cfg.attrs = a;
    cfg.numAttrs = 1;
    cudaLaunchKernelEx(&cfg, kernel, args...);
}

extern "C" void kernel_launch(void* const* d_in, const int* in_sizes, int n_in,
                              void* d_out, int out_size)
{
    // Exact float64 replication of the reference _RESOLUTIONS computation.
    ResArr res;
    double b = exp((log(512.0) - log(16.0)) / 15.0);
    for (int l = 0; l < LEVELS; ++l) {
        double pw;
        if (l == 0)      pw = 1.0;
        else if (l == 1) pw = b;
        else             pw = pow(b, (double)l);
        res.r[l] = (float)floor(16.0 * pw);
    }

    const float2* x      = (const float2*)d_in[0];
    const float2* tables = (const float2*)d_in[1];
    float*        out    = (float*)d_out;

    hist_kernel<<<NPTS / HI_PER / THREADS, THREADS>>>((const float4*)x);
    launch_pdl(scan_kernel, dim3(NSCANBLK), dim3(SCAN_BLK));
    launch_pdl(scatter_kernel, dim3(NPTS / SC_PER / THREADS), dim3(THREADS), x);
    launch_pdl(hashenc_kernel, dim3(NPTS / THREADS), dim3(THREADS),
               tables, out, res);
}